// round 5
// baseline (speedup 1.0000x reference)
#include <cuda_runtime.h>
#include <cuda_bf16.h>

#define BB 512
#define TT 4096
#define RR 16
#define CHUNK 256
#define NCHUNK (TT / CHUNK)   // 16

// Scratch: per-(b, chunk) partial sums of (var_p - var_t)^2 over 256 t's.
__device__ float g_partial[BB * NCHUNK];

__global__ __launch_bounds__(CHUNK) void rcl_partial_kernel(
    const float* __restrict__ pred,
    const float* __restrict__ target,
    const float* __restrict__ mask)
{
    const int b     = blockIdx.y;
    const int chunk = blockIdx.x;
    const int t     = chunk * CHUNK + threadIdx.x;

    // ---- per-b mask stats (broadcast loads, L1-resident) ----
    const float4* m4 = reinterpret_cast<const float4*>(mask + (size_t)b * RR);
    float4 mv[4];
#pragma unroll
    for (int i = 0; i < 4; i++) mv[i] = __ldg(&m4[i]);
    const float* mm = reinterpret_cast<const float*>(mv);

    float n = 0.0f;
#pragma unroll
    for (int r = 0; r < RR; r++) n += mm[r];
    const float n_safe  = fmaxf(n, 2.0f);
    const float inv_ns  = 1.0f / n_safe;
    const float inv_nm1 = 1.0f / (n_safe - 1.0f);

    // ---- load this thread's row: 16 pred + 16 target floats ----
    const size_t base = ((size_t)b * TT + (size_t)t) * RR;
    const float4* p4 = reinterpret_cast<const float4*>(pred + base);
    const float4* q4 = reinterpret_cast<const float4*>(target + base);

    float4 pv[4], qv[4];
#pragma unroll
    for (int i = 0; i < 4; i++) { pv[i] = p4[i]; qv[i] = q4[i]; }
    const float* pp = reinterpret_cast<const float*>(pv);
    const float* qq = reinterpret_cast<const float*>(qv);

    // ---- one-pass masked moments ----
    float sp = 0.0f, spp = 0.0f, st = 0.0f, stt = 0.0f;
#pragma unroll
    for (int r = 0; r < RR; r++) {
        const float m  = mm[r];
        const float mp = m * pp[r];
        const float mt = m * qq[r];
        sp  += mp;
        spp = fmaf(mp, pp[r], spp);
        st  += mt;
        stt = fmaf(mt, qq[r], stt);
    }

    const float mean_p = sp * inv_ns;
    const float mean_t = st * inv_ns;
    // sq = sum m*(x-mean)^2 = sxx - 2*mean*sx + mean^2 * n
    const float sq_p  = spp - 2.0f * mean_p * sp + mean_p * mean_p * n;
    const float sq_t  = stt - 2.0f * mean_t * st + mean_t * mean_t * n;
    const float var_p = sq_p * inv_nm1;
    const float var_t = sq_t * inv_nm1;
    const float d = var_p - var_t;
    float acc = d * d;

    // ---- deterministic block reduction ----
#pragma unroll
    for (int off = 16; off > 0; off >>= 1)
        acc += __shfl_down_sync(0xFFFFFFFFu, acc, off);

    __shared__ float swarp[CHUNK / 32];
    const int lane = threadIdx.x & 31;
    const int wid  = threadIdx.x >> 5;
    if (lane == 0) swarp[wid] = acc;
    __syncthreads();

    if (wid == 0) {
        float v = (lane < (CHUNK / 32)) ? swarp[lane] : 0.0f;
#pragma unroll
        for (int off = 4; off > 0; off >>= 1)
            v += __shfl_down_sync(0xFFFFFFFFu, v, off);
        if (lane == 0) g_partial[b * NCHUNK + chunk] = v;
    }
}

__global__ __launch_bounds__(BB) void rcl_final_kernel(
    const float* __restrict__ mask,
    float* __restrict__ out)
{
    const int b = threadIdx.x;   // 512 threads, one per batch

    float s = 0.0f;
#pragma unroll
    for (int c = 0; c < NCHUNK; c++) s += g_partial[b * NCHUNK + c];
    const float mse = s * (1.0f / (float)TT);

    float n = 0.0f;
#pragma unroll
    for (int r = 0; r < RR; r++) n += mask[(size_t)b * RR + r];

    const float valid = (n > 1.0f) ? 1.0f : 0.0f;
    float tot = valid * mse;
    float cnt = valid;

    // reduce (tot, cnt) over 512 threads: warp shuffles + shared
#pragma unroll
    for (int off = 16; off > 0; off >>= 1) {
        tot += __shfl_down_sync(0xFFFFFFFFu, tot, off);
        cnt += __shfl_down_sync(0xFFFFFFFFu, cnt, off);
    }

    __shared__ float stot[BB / 32];
    __shared__ float scnt[BB / 32];
    const int lane = threadIdx.x & 31;
    const int wid  = threadIdx.x >> 5;
    if (lane == 0) { stot[wid] = tot; scnt[wid] = cnt; }
    __syncthreads();

    if (wid == 0) {
        float vt = (lane < (BB / 32)) ? stot[lane] : 0.0f;
        float vc = (lane < (BB / 32)) ? scnt[lane] : 0.0f;
#pragma unroll
        for (int off = 8; off > 0; off >>= 1) {
            vt += __shfl_down_sync(0xFFFFFFFFu, vt, off);
            vc += __shfl_down_sync(0xFFFFFFFFu, vc, off);
        }
        if (lane == 0) {
            const float loss = (vc > 0.0f) ? (vt / fmaxf(vc, 1.0f)) : 0.0f;
            out[0] = 0.1f * loss;
        }
    }
}

extern "C" void kernel_launch(void* const* d_in, const int* in_sizes, int n_in,
                              void* d_out, int out_size)
{
    const float* pred   = (const float*)d_in[0];
    const float* target = (const float*)d_in[1];
    const float* mask   = (const float*)d_in[2];
    float* out = (float*)d_out;

    dim3 grid(NCHUNK, BB);
    rcl_partial_kernel<<<grid, CHUNK>>>(pred, target, mask);
    rcl_final_kernel<<<1, BB>>>(mask, out);
}

// round 7
// speedup vs baseline: 1.0046x; 1.0046x over previous
#include <cuda_runtime.h>
#include <cuda_bf16.h>

#define BB 512
#define TT 4096
#define RR 16
#define NCH 8                       // chunks per batch
#define ROWS_PER_CHUNK (TT / NCH)   // 512 rows per block
#define THREADS 256                 // 8 warps; warp covers 64 rows (8 iters x 8 rows)

// Scratch: per-(b, chunk) partial sums of (var_p - var_t)^2.
__device__ float g_partial[BB * NCH];

__global__ __launch_bounds__(THREADS) void rcl_partial_kernel(
    const float* __restrict__ pred,
    const float* __restrict__ target,
    const float* __restrict__ mask)
{
    const int b    = blockIdx.y;
    const int ch   = blockIdx.x;
    const int tid  = threadIdx.x;
    const int lane = tid & 31;
    const int wid  = tid >> 5;
    const int sub  = lane & 3;      // which r-chunk [4*sub, 4*sub+4) this lane owns

    // ---- per-b mask stats (L1-broadcast, once per thread) ----
    const float4* m4 = reinterpret_cast<const float4*>(mask + (size_t)b * RR);
    float4 mall[4];
#pragma unroll
    for (int i = 0; i < 4; i++) mall[i] = __ldg(&m4[i]);
    const float* mf = reinterpret_cast<const float*>(mall);
    float n = 0.0f;
#pragma unroll
    for (int r = 0; r < RR; r++) n += mf[r];
    const float4 mv = mall[sub];

    const float n_safe  = fmaxf(n, 2.0f);
    const float inv_ns  = 1.0f / n_safe;
    const float inv_nm1 = 1.0f / (n_safe - 1.0f);

    // ---- this warp's 64 rows: fully coalesced, 8 rows per warp-iteration ----
    const int    row0  = ch * ROWS_PER_CHUNK + wid * 64;
    const size_t fbase = ((size_t)b * TT + (size_t)row0) * RR;   // float index
    const float4* p4 = reinterpret_cast<const float4*>(pred + fbase);
    const float4* q4 = reinterpret_cast<const float4*>(target + fbase);

    float acc = 0.0f;

#pragma unroll 4
    for (int it = 0; it < 8; ++it) {
        // lane loads float4 #(it*32 + lane): warp covers 512 contiguous bytes
        // = rows [row0 + it*8, row0 + it*8 + 8). nL = 4 lines per LDG.128.
        const float4 p = __ldcs(&p4[it * 32 + lane]);
        const float4 q = __ldcs(&q4[it * 32 + lane]);

        // partial masked moments for this lane's 4 elements
        float sp  = mv.x * p.x + mv.y * p.y + mv.z * p.z + mv.w * p.w;
        float spp = fmaf(mv.x * p.x, p.x,
                    fmaf(mv.y * p.y, p.y,
                    fmaf(mv.z * p.z, p.z, (mv.w * p.w) * p.w)));
        float st  = mv.x * q.x + mv.y * q.y + mv.z * q.z + mv.w * q.w;
        float stt = fmaf(mv.x * q.x, q.x,
                    fmaf(mv.y * q.y, q.y,
                    fmaf(mv.z * q.z, q.z, (mv.w * q.w) * q.w)));

        // butterfly across the 4-lane group -> every lane holds full-row sums
#pragma unroll
        for (int o = 1; o < 4; o <<= 1) {
            sp  += __shfl_xor_sync(0xFFFFFFFFu, sp,  o);
            spp += __shfl_xor_sync(0xFFFFFFFFu, spp, o);
            st  += __shfl_xor_sync(0xFFFFFFFFu, st,  o);
            stt += __shfl_xor_sync(0xFFFFFFFFu, stt, o);
        }

        const float mp  = sp * inv_ns;
        const float mt  = st * inv_ns;
        // sum m*(x-mean)^2 = sxx - 2*mean*sx + mean^2 * n
        const float sqp = spp - 2.0f * mp * sp + mp * mp * n;
        const float sqt = stt - 2.0f * mt * st + mt * mt * n;
        const float d   = (sqp - sqt) * inv_nm1;   // var_p - var_t
        acc = fmaf(d, d, acc);
    }

    acc *= 0.25f;   // each row's d^2 is replicated in 4 lanes of its group

    // ---- deterministic block reduction ----
#pragma unroll
    for (int off = 16; off > 0; off >>= 1)
        acc += __shfl_down_sync(0xFFFFFFFFu, acc, off);

    __shared__ float swarp[THREADS / 32];
    if (lane == 0) swarp[wid] = acc;
    __syncthreads();

    if (wid == 0) {
        float v = (lane < (THREADS / 32)) ? swarp[lane] : 0.0f;
#pragma unroll
        for (int off = 4; off > 0; off >>= 1)
            v += __shfl_down_sync(0xFFFFFFFFu, v, off);
        if (lane == 0) g_partial[b * NCH + ch] = v;
    }
}

__global__ __launch_bounds__(BB) void rcl_final_kernel(
    const float* __restrict__ mask,
    float* __restrict__ out)
{
    const int b = threadIdx.x;   // 512 threads, one per batch

    float s = 0.0f;
#pragma unroll
    for (int c = 0; c < NCH; c++) s += g_partial[b * NCH + c];
    const float mse = s * (1.0f / (float)TT);

    float n = 0.0f;
#pragma unroll
    for (int r = 0; r < RR; r++) n += mask[(size_t)b * RR + r];

    const float valid = (n > 1.0f) ? 1.0f : 0.0f;
    float tot = valid * mse;
    float cnt = valid;

#pragma unroll
    for (int off = 16; off > 0; off >>= 1) {
        tot += __shfl_down_sync(0xFFFFFFFFu, tot, off);
        cnt += __shfl_down_sync(0xFFFFFFFFu, cnt, off);
    }

    __shared__ float stot[BB / 32];
    __shared__ float scnt[BB / 32];
    const int lane = threadIdx.x & 31;
    const int wid  = threadIdx.x >> 5;
    if (lane == 0) { stot[wid] = tot; scnt[wid] = cnt; }
    __syncthreads();

    if (wid == 0) {
        float vt = (lane < (BB / 32)) ? stot[lane] : 0.0f;
        float vc = (lane < (BB / 32)) ? scnt[lane] : 0.0f;
#pragma unroll
        for (int off = 8; off > 0; off >>= 1) {
            vt += __shfl_down_sync(0xFFFFFFFFu, vt, off);
            vc += __shfl_down_sync(0xFFFFFFFFu, vc, off);
        }
        if (lane == 0) {
            const float loss = (vc > 0.0f) ? (vt / fmaxf(vc, 1.0f)) : 0.0f;
            out[0] = 0.1f * loss;
        }
    }
}

extern "C" void kernel_launch(void* const* d_in, const int* in_sizes, int n_in,
                              void* d_out, int out_size)
{
    const float* pred   = (const float*)d_in[0];
    const float* target = (const float*)d_in[1];
    const float* mask   = (const float*)d_in[2];
    float* out = (float*)d_out;

    dim3 grid(NCH, BB);
    rcl_partial_kernel<<<grid, THREADS>>>(pred, target, mask);
    rcl_final_kernel<<<1, BB>>>(mask, out);
}